// round 15
// baseline (speedup 1.0000x reference)
#include <cuda_runtime.h>
#include <math.h>

#define CCH   256
#define HW    384
#define NPIX  (HW*HW)        // 147456 elems per channel
#define NQ    (NPIX/4)       // 36864 float4 per channel
#define QPR   (HW/4)         // 96 float4 per row
#define BPC   (NQ/256)       // 144 blocks per channel in fixup
#define INVN  (1.0f/(382.0f*382.0f))

// Per-half partials (all slots written every launch; unique owners -> no init).
__device__ float g_tot [2][CCH][2];        // [which][c][half]
__device__ float g_colp[2][CCH][2][4];     // [which][c][half][col class]
__device__ float g_row [2][CCH][4];        // [which][c][row class] (half h owns classes 2h,2h+1)
__device__ float g_corn[2][CCH][16];       // [which][c][row class*4 + col class]
__device__ float g_cf  [2][CCH];

// ---------------------------------------------------------------------------
// Kernel 1: stats over BOTH inputs + presum write (out = in1 + in2).
// grid = (CCH, 2 halves), block = 384: r0 = tid/96 in [0,4), q = tid%96.
// Half h covers rows [192h, 192h+192); iteration j -> row 192h + 4j + r0.
// Border rows: half0 j=0 r0<2 (rows 0,1); half1 j=47 r0>=2 (rows 382,383).
// The store mixes writes into the read stream -> ~7TB/s regime (measured on
// combine), and (1,1)-channels' final output is already complete after this.
// ---------------------------------------------------------------------------
__global__ void __launch_bounds__(384) stats_presum_kernel(const float* __restrict__ in1,
                                                           const float* __restrict__ in2,
                                                           float4* __restrict__ out) {
    const int c    = blockIdx.x;
    const int half = blockIdx.y;
    const size_t off0 = (size_t)c * NQ + (size_t)half * (192 * QPR);

    const int tid = threadIdx.x;
    const int r0  = tid / 96;          // 0..3
    const int q   = tid - r0 * 96;     // 0..95
    const bool q0  = (q == 0);
    const bool q95 = (q == 95);

    __shared__ float colsh[2][4];
    __shared__ float rowsh[2][2];
    __shared__ float red[12][2];
    if (tid < 8)  ((float*)colsh)[tid] = 0.0f;
    if (tid < 4)  ((float*)rowsh)[tid] = 0.0f;

    const float4* pA = (const float4*)in1 + off0 + (size_t)(r0 * 96 + q);
    const float4* pB = (const float4*)in2 + off0 + (size_t)(r0 * 96 + q);
    float4*       pO = out              + off0 + (size_t)(r0 * 96 + q);

    float totA = 0.0f, totB = 0.0f;
    float a0 = 0.0f, a1 = 0.0f, a2 = 0.0f, a3 = 0.0f;   // in1 col-class accs
    float b0 = 0.0f, b1 = 0.0f, b2 = 0.0f, b3 = 0.0f;   // in2 col-class accs
    float accRA = 0.0f, accRB = 0.0f;
    int   rcls  = -1;                                   // local border row class

    int jstart = 0, jend = 48;

    if (half == 0) {
        // peel j=0: rows 0..3 -> border rows 0,1 (r0 < 2), global classes 0,1
        float4 va = __ldcs(pA);
        float4 vb = __ldcs(pB);
        float4 o; o.x = va.x + vb.x; o.y = va.y + vb.y;
                  o.z = va.z + vb.z; o.w = va.w + vb.w;
        __stcs(pO, o);
        float sA = (va.x + va.y) + (va.z + va.w);
        float sB = (vb.x + vb.y) + (vb.z + vb.w);
        totA += sA; totB += sB;
        if (q0)  { a0 += va.x; a1 += va.y; b0 += vb.x; b1 += vb.y; }
        if (q95) { a2 += va.z; a3 += va.w; b2 += vb.z; b3 += vb.w; }
        if (r0 < 2) {
            accRA = sA; accRB = sB; rcls = r0;
            if (q0)  { g_corn[0][c][r0*4+0] = va.x; g_corn[0][c][r0*4+1] = va.y;
                       g_corn[1][c][r0*4+0] = vb.x; g_corn[1][c][r0*4+1] = vb.y; }
            if (q95) { g_corn[0][c][r0*4+2] = va.z; g_corn[0][c][r0*4+3] = va.w;
                       g_corn[1][c][r0*4+2] = vb.z; g_corn[1][c][r0*4+3] = vb.w; }
        }
        pA += 384; pB += 384; pO += 384;
        jstart = 1;
    } else {
        jend = 47;
    }

    // interior: dual-input stream + presum store
    #pragma unroll 4
    for (int j = jstart; j < jend; j++) {
        float4 va = __ldcs(pA);
        float4 vb = __ldcs(pB);
        float4 o; o.x = va.x + vb.x; o.y = va.y + vb.y;
                  o.z = va.z + vb.z; o.w = va.w + vb.w;
        __stcs(pO, o);
        pA += 384; pB += 384; pO += 384;
        totA += (va.x + va.y) + (va.z + va.w);
        totB += (vb.x + vb.y) + (vb.z + vb.w);
        if (q0)  { a0 += va.x; a1 += va.y; b0 += vb.x; b1 += vb.y; }
        if (q95) { a2 += va.z; a3 += va.w; b2 += vb.z; b3 += vb.w; }
    }

    if (half == 1) {
        // peel j=47: rows 380..383 -> border rows 382,383 (r0 >= 2), classes 2,3
        float4 va = __ldcs(pA);
        float4 vb = __ldcs(pB);
        float4 o; o.x = va.x + vb.x; o.y = va.y + vb.y;
                  o.z = va.z + vb.z; o.w = va.w + vb.w;
        __stcs(pO, o);
        float sA = (va.x + va.y) + (va.z + va.w);
        float sB = (vb.x + vb.y) + (vb.z + vb.w);
        totA += sA; totB += sB;
        if (q0)  { a0 += va.x; a1 += va.y; b0 += vb.x; b1 += vb.y; }
        if (q95) { a2 += va.z; a3 += va.w; b2 += vb.z; b3 += vb.w; }
        if (r0 >= 2) {
            accRA = sA; accRB = sB; rcls = r0 - 2;
            if (q0)  { g_corn[0][c][r0*4+0] = va.x; g_corn[0][c][r0*4+1] = va.y;
                       g_corn[1][c][r0*4+0] = vb.x; g_corn[1][c][r0*4+1] = vb.y; }
            if (q95) { g_corn[0][c][r0*4+2] = va.z; g_corn[0][c][r0*4+3] = va.w;
                       g_corn[1][c][r0*4+2] = vb.z; g_corn[1][c][r0*4+3] = vb.w; }
        }
    }

    __syncthreads();   // shared init ordered before atomics

    if (rcls >= 0) {
        atomicAdd(&rowsh[0][rcls], accRA);
        atomicAdd(&rowsh[1][rcls], accRB);
    }
    if (q0)  { atomicAdd(&colsh[0][0], a0); atomicAdd(&colsh[0][1], a1);
               atomicAdd(&colsh[1][0], b0); atomicAdd(&colsh[1][1], b1); }
    if (q95) { atomicAdd(&colsh[0][2], a2); atomicAdd(&colsh[0][3], a3);
               atomicAdd(&colsh[1][2], b2); atomicAdd(&colsh[1][3], b3); }

    #pragma unroll
    for (int off = 16; off > 0; off >>= 1) {
        totA += __shfl_down_sync(0xffffffffu, totA, off);
        totB += __shfl_down_sync(0xffffffffu, totB, off);
    }
    const int warp = tid >> 5, lane = tid & 31;
    if (lane == 0) { red[warp][0] = totA; red[warp][1] = totB; }
    __syncthreads();

    if (tid < 2) {
        float T = 0.0f;
        #pragma unroll
        for (int w = 0; w < 12; w++) T += red[w][tid];
        g_tot[tid][c][half] = T;
    }
    if (tid < 4) {
        g_colp[0][c][half][tid] = colsh[0][tid];
        g_colp[1][c][half][tid] = colsh[1][tid];
    }
    if (tid >= 4 && tid < 6) {
        const int k = tid - 4;
        g_row[0][c][half*2 + k] = rowsh[0][k];
        g_row[1][c][half*2 + k] = rowsh[1][k];
    }
}

// ---------------------------------------------------------------------------
// Kernel 2: finalize (merge halves -> 9 window sums) + per-oc matvec,
// sigmoid, branch flags -> per-channel combine coefficients. (R12-proven.)
// ---------------------------------------------------------------------------
__global__ void __launch_bounds__(256) coef_kernel(const float* __restrict__ W,
                                                   const float* __restrict__ b) {
    const int oc = blockIdx.x;
    const int ic = threadIdx.x;

    float S[2][9];
    const int ER[3][2] = { {2,3}, {0,3}, {0,1} };
    #pragma unroll
    for (int w = 0; w < 2; w++) {
        float T = g_tot[w][ic][0] + g_tot[w][ic][1];
        float cs0 = g_colp[w][ic][0][0] + g_colp[w][ic][1][0];
        float cs1 = g_colp[w][ic][0][1] + g_colp[w][ic][1][1];
        float cs2 = g_colp[w][ic][0][2] + g_colp[w][ic][1][2];
        float cs3 = g_colp[w][ic][0][3] + g_colp[w][ic][1][3];
        float rs0 = g_row[w][ic][0], rs1 = g_row[w][ic][1],
              rs2 = g_row[w][ic][2], rs3 = g_row[w][ic][3];
        float Rex[3] = { rs2+rs3, rs0+rs3, rs0+rs1 };
        float Cex[3] = { cs2+cs3, cs0+cs3, cs0+cs1 };
        #pragma unroll
        for (int kh = 0; kh < 3; kh++)
            #pragma unroll
            for (int kw = 0; kw < 3; kw++) {
                float cor = 0.0f;
                #pragma unroll
                for (int i = 0; i < 2; i++)
                    #pragma unroll
                    for (int j = 0; j < 2; j++)
                        cor += g_corn[w][ic][ER[kh][i]*4 + ER[kw][j]];
                S[w][kh*3 + kw] = T - Rex[kh] - Cex[kw] + cor;
            }
    }

    const float* wrow = W + (size_t)oc * CCH * 9 + ic * 9;
    float d1 = 0.0f, d2 = 0.0f;
    #pragma unroll
    for (int k = 0; k < 9; k++) {
        float w = wrow[k];
        d1 += w * S[0][k];
        d2 += w * S[1][k];
    }
    #pragma unroll
    for (int off = 16; off > 0; off >>= 1) {
        d1 += __shfl_down_sync(0xffffffffu, d1, off);
        d2 += __shfl_down_sync(0xffffffffu, d2, off);
    }
    __shared__ float s1[8], s2[8];
    int warp = ic >> 5, lane = ic & 31;
    if (lane == 0) { s1[warp] = d1; s2[warp] = d2; }
    __syncthreads();
    if (ic == 0) {
        float D1 = 0.0f, D2 = 0.0f;
        #pragma unroll
        for (int w = 0; w < 8; w++) { D1 += s1[w]; D2 += s2[w]; }
        float bb = b[oc];
        float m1 = bb + D1 * INVN;
        float m2 = bb + D2 * INVN;
        float m3 = bb + (D1 + D2) * INVN;
        float x1 = 1.0f / (1.0f + expf(-m1));
        float x2 = 1.0f / (1.0f + expf(-m2));
        float x3 = 1.0f / (1.0f + expf(-m3));
        bool c1 = (x1 >= x2);
        bool c2 = (x1 <= x2);
        float a1 = (c1 && (x1 >= x3)) ? 1.0f : 0.0f;
        float a2 = (c2 && (x2 >= x3)) ? 1.0f : 0.0f;
        float a3 = ((c1 && (x1 < x3)) || (c2 && (x2 < x3))) ? 1.0f : 0.0f;
        g_cf[0][oc] = a1 + a3;   // multiplies input1
        g_cf[1][oc] = a2 + a3;   // multiplies input2
    }
}

// ---------------------------------------------------------------------------
// Kernel 3: fixup. Presum already wrote out = in1+in2 (correct for (1,1)
// channels, ~60%). Channels with (1,0)/(0,1) overwrite with a pure copy of
// the single needed input (coefficient is exactly 1.0). (1,1) blocks exit
// after 2 scalar loads. Block-uniform, deterministic, graph-safe.
// ---------------------------------------------------------------------------
__global__ void __launch_bounds__(256) fixup_kernel(const float4* __restrict__ in1,
                                                    const float4* __restrict__ in2,
                                                    float4* __restrict__ out) {
    const int ch = blockIdx.x / BPC;
    const float k1 = g_cf[0][ch];
    const float k2 = g_cf[1][ch];
    if (k1 != 0.0f && k2 != 0.0f) return;        // (1,1): presum is final
    const int idx = blockIdx.x * 256 + threadIdx.x;
    const float4* src = (k2 == 0.0f) ? in1 : in2;
    __stcs(out + idx, __ldcs(src + idx));
}

extern "C" void kernel_launch(void* const* d_in, const int* in_sizes, int n_in,
                              void* d_out, int out_size) {
    const float* in1 = (const float*)d_in[0];
    const float* in2 = (const float*)d_in[1];
    const float* W   = (const float*)d_in[2];
    const float* b   = (const float*)d_in[3];
    float4* out = (float4*)d_out;

    stats_presum_kernel<<<dim3(CCH, 2), 384>>>(in1, in2, out);
    coef_kernel<<<CCH, 256>>>(W, b);
    fixup_kernel<<<CCH * BPC, 256>>>((const float4*)in1, (const float4*)in2, out);
}

// round 16
// speedup vs baseline: 1.6500x; 1.6500x over previous
#include <cuda_runtime.h>
#include <math.h>

#define CCH   256
#define HW    384
#define NPIX  (HW*HW)        // 147456 elems per channel
#define NQ    (NPIX/4)       // 36864 float4 per channel
#define QPR   (HW/4)         // 96 float4 per row
#define QPB   1024           // float4 per combine block
#define CBPC  (NQ/QPB)       // 36 combine blocks per channel
#define INVN  (1.0f/(382.0f*382.0f))

// Window sums flattened per input: S[which][c*9 + k], 16B aligned for float4.
__device__ __align__(16) float g_S[2][CCH * 9];
__device__ float g_cf[2][CCH];

// ---------------------------------------------------------------------------
// Kernel 1: per-(input, channel) statistics -> 9 window sums.
// R10-proven shape (53.8us, read-only streaming ceiling ~5.65TB/s).
// 384 threads: r0 = tid/96 in [0,4), q = tid%96. Dual stream A/B halves.
// ---------------------------------------------------------------------------
__global__ void __launch_bounds__(384) stats_kernel(const float* __restrict__ in1,
                                                    const float* __restrict__ in2) {
    const int c     = blockIdx.x;
    const int which = blockIdx.y;
    const float4* x = ((const float4*)(which ? in2 : in1)) + (size_t)c * NQ;

    const int tid = threadIdx.x;
    const int r0  = tid / 96;          // 0..3
    const int q   = tid - r0 * 96;     // 0..95
    const bool q0  = (q == 0);
    const bool q95 = (q == 95);

    __shared__ float corn[16];
    __shared__ float rowsh[4];
    __shared__ float colsh[4];
    __shared__ float red[12];
    if (tid < 4) { rowsh[tid] = 0.0f; colsh[tid] = 0.0f; }

    const float4* pA = x + (size_t)(r0 * 96 + q);            // row r0
    const float4* pB = x + (size_t)((192 + r0) * 96 + q);    // row 192+r0

    float totA = 0.0f, totB = 0.0f;
    float c0 = 0.0f, c1 = 0.0f, c2 = 0.0f, c3 = 0.0f;
    float accR = 0.0f;

    // ---- peel stream A j = 0 (rows 0..3) ----
    {
        float4 v = __ldcs(pA);
        float s = (v.x + v.y) + (v.z + v.w);
        totA += s;
        if (q0)  { c0 += v.x; c1 += v.y; }
        if (q95) { c2 += v.z; c3 += v.w; }
        if (r0 < 2) {
            accR += s;
            if (q0)  { corn[r0*4 + 0] = v.x; corn[r0*4 + 1] = v.y; }
            if (q95) { corn[r0*4 + 2] = v.z; corn[r0*4 + 3] = v.w; }
        }
        pA += 384;
    }

    // ---- dual-stream interior: A j=1..47, B j=48..94 ----
    #pragma unroll 4
    for (int j = 0; j < 47; j++) {
        float4 va = __ldcs(pA);
        float4 vb = __ldcs(pB);
        pA += 384;
        pB += 384;
        totA += (va.x + va.y) + (va.z + va.w);
        totB += (vb.x + vb.y) + (vb.z + vb.w);
        if (q0)  { c0 += va.x + vb.x; c1 += va.y + vb.y; }
        if (q95) { c2 += va.z + vb.z; c3 += va.w + vb.w; }
    }

    // ---- peel stream B j = 95 (rows 380..383) ----
    {
        float4 v = __ldcs(pB);
        float s = (v.x + v.y) + (v.z + v.w);
        totB += s;
        if (q0)  { c0 += v.x; c1 += v.y; }
        if (q95) { c2 += v.z; c3 += v.w; }
        if (r0 >= 2) {
            accR += s;
            if (q0)  { corn[r0*4 + 0] = v.x; corn[r0*4 + 1] = v.y; }
            if (q95) { corn[r0*4 + 2] = v.z; corn[r0*4 + 3] = v.w; }
        }
    }

    __syncthreads();   // rowsh/colsh init + corn stores ordered

    atomicAdd(&rowsh[r0], accR);
    if (q0)  { atomicAdd(&colsh[0], c0); atomicAdd(&colsh[1], c1); }
    if (q95) { atomicAdd(&colsh[2], c2); atomicAdd(&colsh[3], c3); }

    float tot = totA + totB;
    #pragma unroll
    for (int off = 16; off > 0; off >>= 1)
        tot += __shfl_down_sync(0xffffffffu, tot, off);
    int warp = tid >> 5, lane = tid & 31;
    if (lane == 0) red[warp] = tot;
    __syncthreads();

    if (tid == 0) {
        float T = 0.0f;
        #pragma unroll
        for (int w = 0; w < 12; w++) T += red[w];
        const int ER[3][2] = { {2,3}, {0,3}, {0,1} };
        float Rex[3] = { rowsh[2]+rowsh[3], rowsh[0]+rowsh[3], rowsh[0]+rowsh[1] };
        float Cex[3] = { colsh[2]+colsh[3], colsh[0]+colsh[3], colsh[0]+colsh[1] };
        #pragma unroll
        for (int kh = 0; kh < 3; kh++) {
            #pragma unroll
            for (int kw = 0; kw < 3; kw++) {
                float cor = 0.0f;
                #pragma unroll
                for (int i = 0; i < 2; i++)
                    #pragma unroll
                    for (int j = 0; j < 2; j++)
                        cor += corn[ER[kh][i]*4 + ER[kw][j]];
                g_S[which][c * 9 + kh*3 + kw] = T - Rex[kh] - Cex[kw] + cor;
            }
        }
    }
}

// ---------------------------------------------------------------------------
// Kernel 2: vectorized matvec (R13-proven). One block (288 threads) per oc.
// ---------------------------------------------------------------------------
__global__ void __launch_bounds__(288) coef_kernel(const float* __restrict__ W,
                                                   const float* __restrict__ b) {
    const int oc = blockIdx.x;
    const int t  = threadIdx.x;        // 0..287

    const float4* w4 = (const float4*)(W + (size_t)oc * (CCH * 9));
    const float4* s1 = (const float4*)g_S[0];
    const float4* s2 = (const float4*)g_S[1];

    float4 wa = __ldg(w4 + t);
    float4 wb = __ldg(w4 + t + 288);
    float4 x1a = s1[t], x1b = s1[t + 288];
    float4 x2a = s2[t], x2b = s2[t + 288];

    float d1 = (wa.x * x1a.x + wa.y * x1a.y) + (wa.z * x1a.z + wa.w * x1a.w)
             + (wb.x * x1b.x + wb.y * x1b.y) + (wb.z * x1b.z + wb.w * x1b.w);
    float d2 = (wa.x * x2a.x + wa.y * x2a.y) + (wa.z * x2a.z + wa.w * x2a.w)
             + (wb.x * x2b.x + wb.y * x2b.y) + (wb.z * x2b.z + wb.w * x2b.w);

    #pragma unroll
    for (int off = 16; off > 0; off >>= 1) {
        d1 += __shfl_down_sync(0xffffffffu, d1, off);
        d2 += __shfl_down_sync(0xffffffffu, d2, off);
    }
    __shared__ float r1[9], r2[9];
    const int warp = t >> 5, lane = t & 31;
    if (lane == 0) { r1[warp] = d1; r2[warp] = d2; }
    __syncthreads();

    if (t == 0) {
        float D1 = 0.0f, D2 = 0.0f;
        #pragma unroll
        for (int w = 0; w < 9; w++) { D1 += r1[w]; D2 += r2[w]; }
        float bb = b[oc];
        float m1 = bb + D1 * INVN;
        float m2 = bb + D2 * INVN;
        float m3 = bb + (D1 + D2) * INVN;
        float x1 = 1.0f / (1.0f + expf(-m1));
        float x2 = 1.0f / (1.0f + expf(-m2));
        float x3 = 1.0f / (1.0f + expf(-m3));
        bool c1 = (x1 >= x2);
        bool c2 = (x1 <= x2);
        float a1 = (c1 && (x1 >= x3)) ? 1.0f : 0.0f;
        float a2 = (c2 && (x2 >= x3)) ? 1.0f : 0.0f;
        float a3 = ((c1 && (x1 < x3)) || (c2 && (x2 < x3))) ? 1.0f : 0.0f;
        g_cf[0][oc] = a1 + a3;   // multiplies input1
        g_cf[1][oc] = a2 + a3;   // multiplies input2
    }
}

// ---------------------------------------------------------------------------
// Kernel 3: combine with load skipping, WIDENED to 4 float4 per thread.
// grid = CCH*36 blocks of 256 threads; thread t handles quads t, t+256,
// t+512, t+768 of its 1024-quad tile -> 4-8 independent front-batched loads
// (MLP_p1 up to 8), 4 stores, retire. Skip classes as in R10 (proven).
// ---------------------------------------------------------------------------
__global__ void __launch_bounds__(256) combine_kernel(const float4* __restrict__ in1,
                                                      const float4* __restrict__ in2,
                                                      float4* __restrict__ out) {
    const int ch   = blockIdx.x / CBPC;               // 36 blocks per channel
    const size_t base = (size_t)blockIdx.x * QPB + threadIdx.x;
    const float k1 = g_cf[0][ch];
    const float k2 = g_cf[1][ch];

    if (k2 == 0.0f) {                 // (1,0): only input1 needed
        float4 a0 = __ldcs(in1 + base);
        float4 a1 = __ldcs(in1 + base + 256);
        float4 a2 = __ldcs(in1 + base + 512);
        float4 a3 = __ldcs(in1 + base + 768);
        __stcs(out + base,       a0);
        __stcs(out + base + 256, a1);
        __stcs(out + base + 512, a2);
        __stcs(out + base + 768, a3);
    } else if (k1 == 0.0f) {          // (0,1): only input2 needed
        float4 b0 = __ldcs(in2 + base);
        float4 b1 = __ldcs(in2 + base + 256);
        float4 b2 = __ldcs(in2 + base + 512);
        float4 b3 = __ldcs(in2 + base + 768);
        __stcs(out + base,       b0);
        __stcs(out + base + 256, b1);
        __stcs(out + base + 512, b2);
        __stcs(out + base + 768, b3);
    } else {                          // (1,1): out = in1 + in2
        float4 a0 = __ldcs(in1 + base);
        float4 a1 = __ldcs(in1 + base + 256);
        float4 a2 = __ldcs(in1 + base + 512);
        float4 a3 = __ldcs(in1 + base + 768);
        float4 b0 = __ldcs(in2 + base);
        float4 b1 = __ldcs(in2 + base + 256);
        float4 b2 = __ldcs(in2 + base + 512);
        float4 b3 = __ldcs(in2 + base + 768);
        float4 o;
        o.x = a0.x + b0.x; o.y = a0.y + b0.y; o.z = a0.z + b0.z; o.w = a0.w + b0.w;
        __stcs(out + base, o);
        o.x = a1.x + b1.x; o.y = a1.y + b1.y; o.z = a1.z + b1.z; o.w = a1.w + b1.w;
        __stcs(out + base + 256, o);
        o.x = a2.x + b2.x; o.y = a2.y + b2.y; o.z = a2.z + b2.z; o.w = a2.w + b2.w;
        __stcs(out + base + 512, o);
        o.x = a3.x + b3.x; o.y = a3.y + b3.y; o.z = a3.z + b3.z; o.w = a3.w + b3.w;
        __stcs(out + base + 768, o);
    }
}

extern "C" void kernel_launch(void* const* d_in, const int* in_sizes, int n_in,
                              void* d_out, int out_size) {
    const float* in1 = (const float*)d_in[0];
    const float* in2 = (const float*)d_in[1];
    const float* W   = (const float*)d_in[2];
    const float* b   = (const float*)d_in[3];
    float* out = (float*)d_out;

    stats_kernel<<<dim3(CCH, 2), 384>>>(in1, in2);
    coef_kernel<<<CCH, 288>>>(W, b);
    combine_kernel<<<CCH * CBPC, 256>>>((const float4*)in1,
                                        (const float4*)in2,
                                        (float4*)out);
}